// round 11
// baseline (speedup 1.0000x reference)
#include <cuda_runtime.h>
#include <cuda_fp16.h>

// Repacked grid: [B=4][Hg=16][Wg=16][D=8][16ch(pad)] = 131072 floats
__device__ float g_repack[4 * 16 * 16 * 8 * 16];

__global__ void repack_kernel(const float* __restrict__ G) {
    int i = blockIdx.x * blockDim.x + threadIdx.x;  // 131072 threads
    int c = i & 15;
    int t = i >> 4;
    int z = t & 7;  t >>= 3;
    int x = t & 15; t >>= 4;
    int y = t & 15;
    int b = t >> 4;
    float v = 0.0f;
    if (c < 12) {
        v = G[((b * 12 + c) * 8 + z) * 256 + y * 16 + x];
    }
    g_repack[i] = v;
}

union U4 {
    uint4 u;
    __half2 h[4];
};

__global__ __launch_bounds__(256, 5) void slice_apply_kernel(
    const float* __restrict__ guide,
    const float* __restrict__ fr,
    float* __restrict__ out)
{
    // Ta[sy][xl][z]: ch0-7 as 8 halves (16B). addr16 = (sy*64+xl)*8+z -> bank = z.
    // Tb[xl][z]: {sy0 ch8-11, sy1 ch8-11} as 8 halves (16B). bank = z.
    __shared__ uint4 TaS[2 * 64 * 8];   // 16KB
    __shared__ uint4 TbS[64 * 8];       // 8KB

    const int b   = blockIdx.z;
    const int tx  = blockIdx.x;        // x grid-cell (tile 64 px wide)
    const int by  = blockIdx.y;        // 16-row tile index
    const int tid = threadIdx.x;

    // 16-row aligned tiles never cross an fy boundary (boundaries at y=32+64k).
    const int   fy0  = (by - 2) >> 2;  // arithmetic shift
    const float fy0f = (float)fy0;
    const int   gy0  = max(fy0, 0);
    const int   gy1  = min(fy0 + 1, 15);

    // ---- build fp16 tables: 1024 (sy,xl,z) entries, 4 per thread; z lane-fast ----
    {
        const int z    = tid & 7;
        const int rest = tid >> 3;         // 0..31
        const int xlq  = rest & 15;        // 4-px group 0..15
        const int sy   = rest >> 4;
        const int half = xlq >> 3;         // 0: xl<32 (fx0=tx-1), 1: xl>=32

        const int gy  = sy ? gy1 : gy0;
        const int gxa = half ? tx : max(tx - 1, 0);
        const int gxb = half ? min(tx + 1, 15) : tx;

        const float4* s0p = (const float4*)&g_repack[(((b * 16 + gy) * 16 + gxa) * 8 + z) * 16];
        const float4* s1p = (const float4*)&g_repack[(((b * 16 + gy) * 16 + gxb) * 8 + z) * 16];
        const float4 s0a = s0p[0], s0b = s0p[1], s0c = s0p[2];
        const float4 s1a = s1p[0], s1b = s1p[1], s1c = s1p[2];
        const float4 da = make_float4(s1a.x - s0a.x, s1a.y - s0a.y, s1a.z - s0a.z, s1a.w - s0a.w);
        const float4 db = make_float4(s1b.x - s0b.x, s1b.y - s0b.y, s1b.z - s0b.z, s1b.w - s0b.w);
        const float4 dc = make_float4(s1c.x - s0c.x, s1c.y - s0c.y, s1c.z - s0c.z, s1c.w - s0c.w);

        const int   xlb = xlq << 2;
        // wx = (xl+0.5)/64 + (half ? -0.5 : 0.5)
        const float wxb = ((float)xlb + 0.5f) * (1.0f / 64.0f) + (half ? -0.5f : 0.5f);

        #pragma unroll
        for (int k = 0; k < 4; k++) {
            const float wx = wxb + (float)k * (1.0f / 64.0f);
            const float c0 = fmaf(wx, da.x, s0a.x), c1 = fmaf(wx, da.y, s0a.y);
            const float c2 = fmaf(wx, da.z, s0a.z), c3 = fmaf(wx, da.w, s0a.w);
            const float c4 = fmaf(wx, db.x, s0b.x), c5 = fmaf(wx, db.y, s0b.y);
            const float c6 = fmaf(wx, db.z, s0b.z), c7 = fmaf(wx, db.w, s0b.w);
            const float c8 = fmaf(wx, dc.x, s0c.x), c9 = fmaf(wx, dc.y, s0c.y);
            const float cA = fmaf(wx, dc.z, s0c.z), cB = fmaf(wx, dc.w, s0c.w);

            U4 ta;
            ta.h[0] = __floats2half2_rn(c0, c1);
            ta.h[1] = __floats2half2_rn(c2, c3);
            ta.h[2] = __floats2half2_rn(c4, c5);
            ta.h[3] = __floats2half2_rn(c6, c7);
            TaS[(sy * 64 + xlb + k) * 8 + z] = ta.u;

            __half2 tb0 = __floats2half2_rn(c8, c9);
            __half2 tb1 = __floats2half2_rn(cA, cB);
            __half2* tbp = (__half2*)&TbS[(xlb + k) * 8 + z];
            tbp[sy * 2 + 0] = tb0;
            tbp[sy * 2 + 1] = tb1;
        }
    }
    __syncthreads();

    // ---- main: thread = one 4-px quad on one row. 8-lane phases share the quad
    //      column -> table LDS diverges only in z -> conflict-free / broadcast. ----
    const int lane    = tid & 31;
    const int warp    = tid >> 5;
    const int sub     = lane >> 3;                 // 0..3
    const int rphase  = lane & 7;                  // 0..7
    const int quadIdx = ((warp & 3) << 2) + sub;   // 0..15 (4 px each)
    const int row     = ((warp >> 2) << 3) + rphase; // 0..15

    const int x0 = quadIdx << 2;           // local x base 0..60
    const int y  = (by << 4) + row;

    const float wy  = ((float)y + 0.5f) * (1.0f / 64.0f) - 0.5f - fy0f;

    const size_t gBase  = (size_t)b * 1048576u + ((size_t)y << 10) + (size_t)((tx << 6) + x0);
    const size_t frBase = (size_t)b * 3145728u + ((size_t)y << 10) + (size_t)((tx << 6) + x0);

    const float4 g4  = __ldcs((const float4*)&guide[gBase]);
    const float4 fc0 = __ldcs((const float4*)&fr[frBase]);
    const float4 fc1 = __ldcs((const float4*)&fr[frBase + 1048576u]);
    const float4 fc2 = __ldcs((const float4*)&fr[frBase + 2097152u]);

    const float ga[4]  = {g4.x, g4.y, g4.z, g4.w};
    const float f0a[4] = {fc0.x, fc0.y, fc0.z, fc0.w};
    const float f1a[4] = {fc1.x, fc1.y, fc1.z, fc1.w};
    const float f2a[4] = {fc2.x, fc2.y, fc2.z, fc2.w};

    float o0[4], o1[4], o2[4];

    #pragma unroll
    for (int p = 0; p < 4; p++) {
        const float gz   = ga[p] * 8.0f - 0.5f;
        const float fz0f = floorf(gz);
        const float wz   = gz - fz0f;
        const int   fz0  = (int)fz0f;
        const int   z0   = max(fz0, 0);
        const int   z1   = min(fz0 + 1, 7);

        const __half2 hw0 = __float2half2_rn(1.0f - wz);
        const __half2 hw1 = __float2half2_rn(wz);

        const int eb = (x0 + p) * 8;      // entry base for this xl

        U4 a00, a01, a10, a11, b0, b1;
        a00.u = TaS[eb + z0];
        a01.u = TaS[eb + z1];
        a10.u = TaS[512 + eb + z0];
        a11.u = TaS[512 + eb + z1];
        b0.u  = TbS[eb + z0];
        b1.u  = TbS[eb + z1];

        // z-combine in fp16 (weights identical for both sy)
        __half2 ca0[4], ca1[4], cb[4];
        #pragma unroll
        for (int i = 0; i < 4; i++) {
            ca0[i] = __hfma2(hw0, a00.h[i], __hmul2(hw1, a01.h[i]));
            ca1[i] = __hfma2(hw0, a10.h[i], __hmul2(hw1, a11.h[i]));
            cb[i]  = __hfma2(hw0, b0.h[i],  __hmul2(hw1, b1.h[i]));
        }

        // convert + y-lerp in fp32
        float c[12];
        #pragma unroll
        for (int i = 0; i < 4; i++) {
            const float2 u0 = __half22float2(ca0[i]);
            const float2 u1 = __half22float2(ca1[i]);
            c[2 * i]     = fmaf(wy, u1.x - u0.x, u0.x);
            c[2 * i + 1] = fmaf(wy, u1.y - u0.y, u0.y);
        }
        {
            const float2 s0l = __half22float2(cb[0]);   // sy0 ch8,9
            const float2 s0h = __half22float2(cb[1]);   // sy0 ch10,11
            const float2 s1l = __half22float2(cb[2]);   // sy1 ch8,9
            const float2 s1h = __half22float2(cb[3]);   // sy1 ch10,11
            c[8]  = fmaf(wy, s1l.x - s0l.x, s0l.x);
            c[9]  = fmaf(wy, s1l.y - s0l.y, s0l.y);
            c[10] = fmaf(wy, s1h.x - s0h.x, s0h.x);
            c[11] = fmaf(wy, s1h.y - s0h.y, s0h.y);
        }

        const float f0p = f0a[p], f1p = f1a[p], f2p = f2a[p];
        o0[p] = fmaf(c[0], f0p, fmaf(c[1],  f1p, fmaf(c[2],  f2p, c[3])));
        o1[p] = fmaf(c[4], f0p, fmaf(c[5],  f1p, fmaf(c[6],  f2p, c[7])));
        o2[p] = fmaf(c[8], f0p, fmaf(c[9],  f1p, fmaf(c[10], f2p, c[11])));
    }

    __stcs((float4*)&out[frBase],            make_float4(o0[0], o0[1], o0[2], o0[3]));
    __stcs((float4*)&out[frBase + 1048576u], make_float4(o1[0], o1[1], o1[2], o1[3]));
    __stcs((float4*)&out[frBase + 2097152u], make_float4(o2[0], o2[1], o2[2], o2[3]));
}

extern "C" void kernel_launch(void* const* d_in, const int* in_sizes, int n_in,
                              void* d_out, int out_size) {
    const float* G     = nullptr;
    const float* guide = nullptr;
    const float* fr    = nullptr;
    for (int i = 0; i < n_in; i++) {
        if (in_sizes[i] == 98304)          G     = (const float*)d_in[i];
        else if (in_sizes[i] == 4194304)   guide = (const float*)d_in[i];
        else if (in_sizes[i] == 12582912)  fr    = (const float*)d_in[i];
    }
    if (!G)     G     = (const float*)d_in[0];
    if (!guide) guide = (const float*)d_in[1];
    if (!fr)    fr    = (const float*)d_in[2];

    float* out = (float*)d_out;

    repack_kernel<<<512, 256>>>(G);

    dim3 grid(16, 64, 4);   // x-tiles(64px), y-tiles(16rows), batch
    slice_apply_kernel<<<grid, 256>>>(guide, fr, out);
}

// round 12
// speedup vs baseline: 1.2040x; 1.2040x over previous
#include <cuda_runtime.h>
#include <cuda_fp16.h>

// Repacked grid: [B=4][Hg=16][Wg=16][D=8][16ch(pad)] = 131072 floats
__device__ float g_repack[4 * 16 * 16 * 8 * 16];

__global__ void repack_kernel(const float* __restrict__ G) {
    int i = blockIdx.x * blockDim.x + threadIdx.x;  // 131072 threads
    int c = i & 15;
    int t = i >> 4;
    int z = t & 7;  t >>= 3;
    int x = t & 15; t >>= 4;
    int y = t & 15;
    int b = t >> 4;
    float v = 0.0f;
    if (c < 12) {
        v = G[((b * 12 + c) * 8 + z) * 256 + y * 16 + x];
    }
    g_repack[i] = v;
}

union U4 {
    uint4 u;
    __half2 h[4];
};

__global__ __launch_bounds__(256, 4) void slice_apply_kernel(
    const float* __restrict__ guide,
    const float* __restrict__ fr,
    float* __restrict__ out)
{
    // Ta[sy(3)][xl(64)][z(8)]: ch0-7 fp16 (16B). addr16 mod 8 = z -> conflict-free.
    // TbL/TbU[xl][z]: {syA ch8-11, syB ch8-11} fp16 (16B). A,B = (0,1) / (1,2).
    __shared__ uint4 TaS[3 * 64 * 8];   // 24KB
    __shared__ uint4 TbL[64 * 8];       // 8KB
    __shared__ uint4 TbU[64 * 8];       // 8KB

    const int b   = blockIdx.z;
    const int tx  = blockIdx.x;        // x grid-cell (tile 64 px wide)
    const int by  = blockIdx.y;        // 64-row tile index (= y grid-cell)
    const int r0  = by << 6;
    const int tid = threadIdx.x;

    // Rows [r0, r0+32) have fy0 = by-1 (slots 0,1); rows [r0+32, r0+64) have
    // fy0 = by (slots 1,2). Slot s -> grid y = clamp(by-1+s, 0, 15).

    // ---- build fp16 tables: 3 sy-slots x 64 xl x 8 z; z lane-fast ----
    {
        const int z   = tid & 7;
        const int g0  = tid >> 3;          // group 0..31
        #pragma unroll
        for (int pass = 0; pass < 2; pass++) {
            const int g = (pass == 0) ? g0 : (32 + g0);
            if (g >= 48) break;            // groups 0..47 = (sy 0..2) x (xlq 0..15)
            const int sy  = g >> 4;
            const int xlq = g & 15;
            const int half = xlq >> 3;     // 0: xl<32 (fx0=tx-1), 1: xl>=32

            const int gy  = min(max(by - 1 + sy, 0), 15);
            const int gxa = half ? tx : max(tx - 1, 0);
            const int gxb = half ? min(tx + 1, 15) : tx;

            const float4* s0p = (const float4*)&g_repack[(((b * 16 + gy) * 16 + gxa) * 8 + z) * 16];
            const float4* s1p = (const float4*)&g_repack[(((b * 16 + gy) * 16 + gxb) * 8 + z) * 16];
            const float4 s0a = s0p[0], s0b = s0p[1], s0c = s0p[2];
            const float4 s1a = s1p[0], s1b = s1p[1], s1c = s1p[2];
            const float4 da = make_float4(s1a.x - s0a.x, s1a.y - s0a.y, s1a.z - s0a.z, s1a.w - s0a.w);
            const float4 db = make_float4(s1b.x - s0b.x, s1b.y - s0b.y, s1b.z - s0b.z, s1b.w - s0b.w);
            const float4 dc = make_float4(s1c.x - s0c.x, s1c.y - s0c.y, s1c.z - s0c.z, s1c.w - s0c.w);

            const int   xlb = xlq << 2;
            // wx = (xl+0.5)/64 + (half ? -0.5 : 0.5)
            const float wxb = ((float)xlb + 0.5f) * (1.0f / 64.0f) + (half ? -0.5f : 0.5f);

            #pragma unroll
            for (int k = 0; k < 4; k++) {
                const float wx = wxb + (float)k * (1.0f / 64.0f);
                const float c0 = fmaf(wx, da.x, s0a.x), c1 = fmaf(wx, da.y, s0a.y);
                const float c2 = fmaf(wx, da.z, s0a.z), c3 = fmaf(wx, da.w, s0a.w);
                const float c4 = fmaf(wx, db.x, s0b.x), c5 = fmaf(wx, db.y, s0b.y);
                const float c6 = fmaf(wx, db.z, s0b.z), c7 = fmaf(wx, db.w, s0b.w);
                const float c8 = fmaf(wx, dc.x, s0c.x), c9 = fmaf(wx, dc.y, s0c.y);
                const float cA = fmaf(wx, dc.z, s0c.z), cB = fmaf(wx, dc.w, s0c.w);

                U4 ta;
                ta.h[0] = __floats2half2_rn(c0, c1);
                ta.h[1] = __floats2half2_rn(c2, c3);
                ta.h[2] = __floats2half2_rn(c4, c5);
                ta.h[3] = __floats2half2_rn(c6, c7);
                const int e = (xlb + k) * 8 + z;
                TaS[sy * 512 + e] = ta.u;

                const __half2 t89 = __floats2half2_rn(c8, c9);
                const __half2 tAB = __floats2half2_rn(cA, cB);
                if (sy == 0) {
                    __half2* p = (__half2*)&TbL[e];
                    p[0] = t89; p[1] = tAB;
                } else if (sy == 1) {
                    __half2* p = (__half2*)&TbL[e];
                    p[2] = t89; p[3] = tAB;
                    __half2* q = (__half2*)&TbU[e];
                    q[0] = t89; q[1] = tAB;
                } else {
                    __half2* q = (__half2*)&TbU[e];
                    q[2] = t89; q[3] = tAB;
                }
            }
        }
    }
    __syncthreads();

    // ---- main: thread = 4-px quads; 8-lane phases share the xl chunk ->
    //      table LDS diverges only in z -> conflict-free / broadcast. ----
    const int lane   = tid & 31;
    const int warp   = tid >> 5;
    const int sub    = lane >> 3;          // 0..3
    const int rphase = lane & 7;           // 0..7
    const int chunk  = ((warp & 1) << 2) + sub;       // 0..7  (8 px each)
    const int rowLo  = ((warp >> 1) << 3) + rphase;   // 0..31

    const int x0 = chunk << 3;             // local x base 0..56

    #pragma unroll
    for (int rr = 0; rr < 2; rr++) {       // lower / upper 32-row half
        const int row = rowLo + (rr << 5);
        const int y   = r0 + row;

        // fy0 = by-1+rr for this half
        const float wy = ((float)y + 0.5f) * (1.0f / 64.0f) - 0.5f - (float)(by - 1 + rr);

        const int  syOff = rr << 9;        // 0 or 512 (slot base in TaS)
        const uint4* Tb  = rr ? TbU : TbL;

        const size_t gBase  = (size_t)b * 1048576u + ((size_t)y << 10) + (size_t)((tx << 6) + x0);
        const size_t frBase = (size_t)b * 3145728u + ((size_t)y << 10) + (size_t)((tx << 6) + x0);

        #pragma unroll
        for (int q = 0; q < 2; q++) {      // two 4-px quads
            const int qo = q << 2;
            const float4 g4  = __ldcs((const float4*)&guide[gBase + qo]);
            const float4 fc0 = __ldcs((const float4*)&fr[frBase + qo]);
            const float4 fc1 = __ldcs((const float4*)&fr[frBase + qo + 1048576u]);
            const float4 fc2 = __ldcs((const float4*)&fr[frBase + qo + 2097152u]);

            const float ga[4]  = {g4.x, g4.y, g4.z, g4.w};
            const float f0a[4] = {fc0.x, fc0.y, fc0.z, fc0.w};
            const float f1a[4] = {fc1.x, fc1.y, fc1.z, fc1.w};
            const float f2a[4] = {fc2.x, fc2.y, fc2.z, fc2.w};

            float o0[4], o1[4], o2[4];

            #pragma unroll
            for (int p = 0; p < 4; p++) {
                const float gz   = ga[p] * 8.0f - 0.5f;
                const float fz0f = floorf(gz);
                const float wz   = gz - fz0f;
                const int   fz0  = (int)fz0f;
                const int   z0   = max(fz0, 0);
                const int   z1   = min(fz0 + 1, 7);

                const __half2 hw0 = __float2half2_rn(1.0f - wz);
                const __half2 hw1 = __float2half2_rn(wz);

                const int eb = (x0 + qo + p) * 8;     // entry base for this xl

                U4 a00, a01, a10, a11, b0, b1;
                a00.u = TaS[syOff + eb + z0];
                a01.u = TaS[syOff + eb + z1];
                a10.u = TaS[syOff + 512 + eb + z0];
                a11.u = TaS[syOff + 512 + eb + z1];
                b0.u  = Tb[eb + z0];
                b1.u  = Tb[eb + z1];

                // z-combine in fp16 (weights identical for both sy)
                __half2 ca0[4], ca1[4], cb[4];
                #pragma unroll
                for (int i = 0; i < 4; i++) {
                    ca0[i] = __hfma2(hw0, a00.h[i], __hmul2(hw1, a01.h[i]));
                    ca1[i] = __hfma2(hw0, a10.h[i], __hmul2(hw1, a11.h[i]));
                    cb[i]  = __hfma2(hw0, b0.h[i],  __hmul2(hw1, b1.h[i]));
                }

                // convert + y-lerp in fp32
                float c[12];
                #pragma unroll
                for (int i = 0; i < 4; i++) {
                    const float2 u0 = __half22float2(ca0[i]);
                    const float2 u1 = __half22float2(ca1[i]);
                    c[2 * i]     = fmaf(wy, u1.x - u0.x, u0.x);
                    c[2 * i + 1] = fmaf(wy, u1.y - u0.y, u0.y);
                }
                {
                    const float2 s0l = __half22float2(cb[0]);   // syA ch8,9
                    const float2 s0h = __half22float2(cb[1]);   // syA ch10,11
                    const float2 s1l = __half22float2(cb[2]);   // syB ch8,9
                    const float2 s1h = __half22float2(cb[3]);   // syB ch10,11
                    c[8]  = fmaf(wy, s1l.x - s0l.x, s0l.x);
                    c[9]  = fmaf(wy, s1l.y - s0l.y, s0l.y);
                    c[10] = fmaf(wy, s1h.x - s0h.x, s0h.x);
                    c[11] = fmaf(wy, s1h.y - s0h.y, s0h.y);
                }

                const float f0p = f0a[p], f1p = f1a[p], f2p = f2a[p];
                o0[p] = fmaf(c[0], f0p, fmaf(c[1],  f1p, fmaf(c[2],  f2p, c[3])));
                o1[p] = fmaf(c[4], f0p, fmaf(c[5],  f1p, fmaf(c[6],  f2p, c[7])));
                o2[p] = fmaf(c[8], f0p, fmaf(c[9],  f1p, fmaf(c[10], f2p, c[11])));
            }

            __stcs((float4*)&out[frBase + qo],            make_float4(o0[0], o0[1], o0[2], o0[3]));
            __stcs((float4*)&out[frBase + qo + 1048576u], make_float4(o1[0], o1[1], o1[2], o1[3]));
            __stcs((float4*)&out[frBase + qo + 2097152u], make_float4(o2[0], o2[1], o2[2], o2[3]));
        }
    }
}

extern "C" void kernel_launch(void* const* d_in, const int* in_sizes, int n_in,
                              void* d_out, int out_size) {
    const float* G     = nullptr;
    const float* guide = nullptr;
    const float* fr    = nullptr;
    for (int i = 0; i < n_in; i++) {
        if (in_sizes[i] == 98304)          G     = (const float*)d_in[i];
        else if (in_sizes[i] == 4194304)   guide = (const float*)d_in[i];
        else if (in_sizes[i] == 12582912)  fr    = (const float*)d_in[i];
    }
    if (!G)     G     = (const float*)d_in[0];
    if (!guide) guide = (const float*)d_in[1];
    if (!fr)    fr    = (const float*)d_in[2];

    float* out = (float*)d_out;

    repack_kernel<<<512, 256>>>(G);

    dim3 grid(16, 16, 4);   // x-tiles(64px), y-tiles(64rows), batch
    slice_apply_kernel<<<grid, 256>>>(guide, fr, out);
}

// round 13
// speedup vs baseline: 1.9014x; 1.5793x over previous
#include <cuda_runtime.h>
#include <cuda_fp16.h>

// Repacked grid: [B=4][Hg=16][Wg=16][D=8][16ch(pad)] = 131072 floats
__device__ float g_repack[4 * 16 * 16 * 8 * 16];

__global__ void repack_kernel(const float* __restrict__ G) {
    int i = blockIdx.x * blockDim.x + threadIdx.x;  // 131072 threads
    int c = i & 15;
    int t = i >> 4;
    int z = t & 7;  t >>= 3;
    int x = t & 15; t >>= 4;
    int y = t & 15;
    int b = t >> 4;
    float v = 0.0f;
    if (c < 12) {
        v = G[((b * 12 + c) * 8 + z) * 256 + y * 16 + x];
    }
    g_repack[i] = v;
}

union U4 {
    uint4 u;
    __half2 h[4];
};

__global__ __launch_bounds__(256, 4) void slice_apply_kernel(
    const float* __restrict__ guide,
    const float* __restrict__ fr,
    float* __restrict__ out)
{
    // Ta[sy(3)][z(8)][p(4)][xq(16)] 16B entries (ch0-7 fp16).
    //   bank16 = xq mod 8  -> phases of 8 consecutive quads are conflict-free,
    //   independent of per-lane z.
    // TbL/TbU[z(8)][p(4)][xq(16)] 16B: {syA ch8-11, syB ch8-11}, A,B=(0,1)/(1,2).
    __shared__ uint4 TaS[3 * 8 * 4 * 16];   // 24KB
    __shared__ uint4 TbL[8 * 4 * 16];       // 8KB
    __shared__ uint4 TbU[8 * 4 * 16];       // 8KB

    const int b   = blockIdx.z;
    const int tx  = blockIdx.x;        // x grid-cell (tile 64 px wide)
    const int by  = blockIdx.y;        // 64-row tile index (= y grid-cell)
    const int r0  = by << 6;
    const int tid = threadIdx.x;

    // ---- build: 384 jobs = (sy3, z8, xq16); each job writes p=0..3 entries ----
    #pragma unroll
    for (int pass = 0; pass < 2; pass++) {
        if (pass == 1 && tid >= 128) break;
        const int j   = pass ? (256 + tid) : tid;
        const int xq  = j & 15;
        const int rest = j >> 4;           // 0..23
        const int z   = rest & 7;
        const int sy  = rest >> 3;         // 0..2
        const int half = xq >> 3;          // 0: xl<32 (fx0=tx-1), 1: xl>=32

        const int gy  = min(max(by - 1 + sy, 0), 15);
        const int gxa = half ? tx : max(tx - 1, 0);
        const int gxb = half ? min(tx + 1, 15) : tx;

        const float4* s0p = (const float4*)&g_repack[(((b * 16 + gy) * 16 + gxa) * 8 + z) * 16];
        const float4* s1p = (const float4*)&g_repack[(((b * 16 + gy) * 16 + gxb) * 8 + z) * 16];
        const float4 s0a = s0p[0], s0b = s0p[1], s0c = s0p[2];
        const float4 s1a = s1p[0], s1b = s1p[1], s1c = s1p[2];
        const float4 da = make_float4(s1a.x - s0a.x, s1a.y - s0a.y, s1a.z - s0a.z, s1a.w - s0a.w);
        const float4 db = make_float4(s1b.x - s0b.x, s1b.y - s0b.y, s1b.z - s0b.z, s1b.w - s0b.w);
        const float4 dc = make_float4(s1c.x - s0c.x, s1c.y - s0c.y, s1c.z - s0c.z, s1c.w - s0c.w);

        // wx = (xl+0.5)/64 + (half ? -0.5 : 0.5), xl = xq*4 + p
        const float wxb = ((float)(xq << 2) + 0.5f) * (1.0f / 64.0f) + (half ? -0.5f : 0.5f);

        #pragma unroll
        for (int p = 0; p < 4; p++) {
            const float wx = wxb + (float)p * (1.0f / 64.0f);
            const float c0 = fmaf(wx, da.x, s0a.x), c1 = fmaf(wx, da.y, s0a.y);
            const float c2 = fmaf(wx, da.z, s0a.z), c3 = fmaf(wx, da.w, s0a.w);
            const float c4 = fmaf(wx, db.x, s0b.x), c5 = fmaf(wx, db.y, s0b.y);
            const float c6 = fmaf(wx, db.z, s0b.z), c7 = fmaf(wx, db.w, s0b.w);
            const float c8 = fmaf(wx, dc.x, s0c.x), c9 = fmaf(wx, dc.y, s0c.y);
            const float cA = fmaf(wx, dc.z, s0c.z), cB = fmaf(wx, dc.w, s0c.w);

            U4 ta;
            ta.h[0] = __floats2half2_rn(c0, c1);
            ta.h[1] = __floats2half2_rn(c2, c3);
            ta.h[2] = __floats2half2_rn(c4, c5);
            ta.h[3] = __floats2half2_rn(c6, c7);
            TaS[(sy * 32 + z * 4 + p) * 16 + xq] = ta.u;

            const __half2 t89 = __floats2half2_rn(c8, c9);
            const __half2 tAB = __floats2half2_rn(cA, cB);
            const int e = (z * 4 + p) * 16 + xq;
            if (sy == 0) {
                __half2* q = (__half2*)&TbL[e];
                q[0] = t89; q[1] = tAB;
            } else if (sy == 1) {
                __half2* q = (__half2*)&TbL[e];
                q[2] = t89; q[3] = tAB;
                __half2* r = (__half2*)&TbU[e];
                r[0] = t89; r[1] = tAB;
            } else {
                __half2* r = (__half2*)&TbU[e];
                r[2] = t89; r[3] = tAB;
            }
        }
    }
    __syncthreads();

    // ---- main: lane = (r 0..3)*8 + qx(0..7). Phase = 8 consecutive quads on
    //      one row -> global LDG/STG hit full 128B lines; table LDS banks = xq
    //      mod 8 -> conflict-free regardless of z. ----
    const int lane = tid & 31;
    const int warp = tid >> 5;
    const int r    = lane >> 3;            // 0..3 row within group
    const int qx   = lane & 7;             // 0..7 quad within 32px half

    #pragma unroll
    for (int i = 0; i < 4; i++) {
        const int u      = warp + (i << 3);     // 0..31
        const int rowgrp = u >> 1;              // 0..15 (4 rows each)
        const int half   = u & 1;
        const int rr     = rowgrp >> 3;         // 0 lower / 1 upper 32 rows

        const int xqg = (half << 3) + qx;       // 0..15
        const int row = (rowgrp << 2) + r;
        const int y   = r0 + row;
        const int x   = (tx << 6) + (xqg << 2);

        // fy0 = by-1+rr for this half
        const float wy = ((float)y + 0.5f) * (1.0f / 64.0f) - 0.5f - (float)(by - 1 + rr);

        const int  syOff = rr << 9;             // 0 or 512 (sy slot base in TaS)
        const uint4* Tb  = rr ? TbU : TbL;

        const size_t gBase  = (size_t)b * 1048576u + ((size_t)y << 10) + (size_t)x;
        const size_t frBase = (size_t)b * 3145728u + ((size_t)y << 10) + (size_t)x;

        const float4 g4  = __ldcs((const float4*)&guide[gBase]);
        const float4 fc0 = __ldcs((const float4*)&fr[frBase]);
        const float4 fc1 = __ldcs((const float4*)&fr[frBase + 1048576u]);
        const float4 fc2 = __ldcs((const float4*)&fr[frBase + 2097152u]);

        const float ga[4]  = {g4.x, g4.y, g4.z, g4.w};
        const float f0a[4] = {fc0.x, fc0.y, fc0.z, fc0.w};
        const float f1a[4] = {fc1.x, fc1.y, fc1.z, fc1.w};
        const float f2a[4] = {fc2.x, fc2.y, fc2.z, fc2.w};

        float o0[4], o1[4], o2[4];

        #pragma unroll
        for (int p = 0; p < 4; p++) {
            const float gz   = ga[p] * 8.0f - 0.5f;
            const float fz0f = floorf(gz);
            const float wz   = gz - fz0f;
            const int   fz0  = (int)fz0f;
            const int   z0   = max(fz0, 0);
            const int   z1   = min(fz0 + 1, 7);

            const __half2 hw0 = __float2half2_rn(1.0f - wz);
            const __half2 hw1 = __float2half2_rn(wz);

            const int e0 = (z0 * 4 + p) * 16 + xqg;
            const int e1 = (z1 * 4 + p) * 16 + xqg;

            U4 a00, a01, a10, a11, b0, b1;
            a00.u = TaS[syOff + e0];
            a01.u = TaS[syOff + e1];
            a10.u = TaS[syOff + 512 + e0];
            a11.u = TaS[syOff + 512 + e1];
            b0.u  = Tb[e0];
            b1.u  = Tb[e1];

            // z-combine in fp16 (weights identical for both sy)
            __half2 ca0[4], ca1[4], cb[4];
            #pragma unroll
            for (int k = 0; k < 4; k++) {
                ca0[k] = __hfma2(hw0, a00.h[k], __hmul2(hw1, a01.h[k]));
                ca1[k] = __hfma2(hw0, a10.h[k], __hmul2(hw1, a11.h[k]));
                cb[k]  = __hfma2(hw0, b0.h[k],  __hmul2(hw1, b1.h[k]));
            }

            // convert + y-lerp in fp32
            float c[12];
            #pragma unroll
            for (int k = 0; k < 4; k++) {
                const float2 u0 = __half22float2(ca0[k]);
                const float2 u1 = __half22float2(ca1[k]);
                c[2 * k]     = fmaf(wy, u1.x - u0.x, u0.x);
                c[2 * k + 1] = fmaf(wy, u1.y - u0.y, u0.y);
            }
            {
                const float2 s0l = __half22float2(cb[0]);   // syA ch8,9
                const float2 s0h = __half22float2(cb[1]);   // syA ch10,11
                const float2 s1l = __half22float2(cb[2]);   // syB ch8,9
                const float2 s1h = __half22float2(cb[3]);   // syB ch10,11
                c[8]  = fmaf(wy, s1l.x - s0l.x, s0l.x);
                c[9]  = fmaf(wy, s1l.y - s0l.y, s0l.y);
                c[10] = fmaf(wy, s1h.x - s0h.x, s0h.x);
                c[11] = fmaf(wy, s1h.y - s0h.y, s0h.y);
            }

            const float f0p = f0a[p], f1p = f1a[p], f2p = f2a[p];
            o0[p] = fmaf(c[0], f0p, fmaf(c[1],  f1p, fmaf(c[2],  f2p, c[3])));
            o1[p] = fmaf(c[4], f0p, fmaf(c[5],  f1p, fmaf(c[6],  f2p, c[7])));
            o2[p] = fmaf(c[8], f0p, fmaf(c[9],  f1p, fmaf(c[10], f2p, c[11])));
        }

        __stcs((float4*)&out[frBase],            make_float4(o0[0], o0[1], o0[2], o0[3]));
        __stcs((float4*)&out[frBase + 1048576u], make_float4(o1[0], o1[1], o1[2], o1[3]));
        __stcs((float4*)&out[frBase + 2097152u], make_float4(o2[0], o2[1], o2[2], o2[3]));
    }
}

extern "C" void kernel_launch(void* const* d_in, const int* in_sizes, int n_in,
                              void* d_out, int out_size) {
    const float* G     = nullptr;
    const float* guide = nullptr;
    const float* fr    = nullptr;
    for (int i = 0; i < n_in; i++) {
        if (in_sizes[i] == 98304)          G     = (const float*)d_in[i];
        else if (in_sizes[i] == 4194304)   guide = (const float*)d_in[i];
        else if (in_sizes[i] == 12582912)  fr    = (const float*)d_in[i];
    }
    if (!G)     G     = (const float*)d_in[0];
    if (!guide) guide = (const float*)d_in[1];
    if (!fr)    fr    = (const float*)d_in[2];

    float* out = (float*)d_out;

    repack_kernel<<<512, 256>>>(G);

    dim3 grid(16, 16, 4);   // x-tiles(64px), y-tiles(64rows), batch
    slice_apply_kernel<<<grid, 256>>>(guide, fr, out);
}